// round 7
// baseline (speedup 1.0000x reference)
#include <cuda_runtime.h>
#include <cstdint>

#define HS    128
#define KITER 40
#define NIMG  256
#define RPC   16            // rows per CTA
#define NCTA  8             // cluster size (8 * 16 = 128 rows)
#define S     132           // padded row stride (floats)
#define NTHR  256
#define NBLK  (KITER/2)     // 20 two-iteration blocks

// smem layout (floats)
#define CR_F    (5*8*NTHR*2)          // cr_main: 10240 u64 = 20480 floats
#define VA_F    (20*S)                // rows -2..17  (idx = global+2)
#define VB_F    (18*S)                // rows -1..16  (idx = global+1)
#define RS_F    (6*S)                 // r strip: rows -2..0, 15..17
#define EXP_F   (2*4*S)               // export: 2 parities x 4 rows
#define SM_FLOATS (CR_F + VA_F + VB_F + RS_F + EXP_F + 90 + 90 + 16)
#define SMEM_BYTES (SM_FLOATS*4)

__device__ float g_eff[19];   // collapsed h->r conv weights (18) + bias

// ---------------- prep: collapse h_w/h_b/r_w into 2x3x3 eff conv ----------------
__global__ void vin_prep(const float* __restrict__ h_w,
                         const float* __restrict__ h_b,
                         const float* __restrict__ r_w) {
    int t = threadIdx.x;
    if (t < 18) {
        float s = 0.f;
        for (int c = 0; c < 150; ++c) s += r_w[c] * h_w[c*18 + t];
        g_eff[t] = s;
    } else if (t == 18) {
        float s = 0.f;
        for (int c = 0; c < 150; ++c) s += r_w[c] * h_b[c];
        g_eff[18] = s;
    }
}

// ---------------- f32x2 / PTX helpers ----------------
__device__ __forceinline__ unsigned long long dup2(float x) {
    unsigned long long d;
    asm("mov.b64 %0, {%1, %1};" : "=l"(d) : "f"(x));
    return d;
}
__device__ __forceinline__ unsigned long long fma2(unsigned long long a,
                                                   unsigned long long b,
                                                   unsigned long long c) {
    unsigned long long d;
    asm("fma.rn.f32x2 %0, %1, %2, %3;" : "=l"(d) : "l"(a), "l"(b), "l"(c));
    return d;
}
__device__ __forceinline__ unsigned long long mul2(unsigned long long a,
                                                   unsigned long long b) {
    unsigned long long d;
    asm("mul.rn.f32x2 %0, %1, %2;" : "=l"(d) : "l"(a), "l"(b));
    return d;
}
__device__ __forceinline__ float2 u2f(unsigned long long u) {
    float2 f;
    asm("mov.b64 {%0, %1}, %2;" : "=f"(f.x), "=f"(f.y) : "l"(u));
    return f;
}
__device__ __forceinline__ uint32_t smem_u32(const void* p) {
    uint32_t a;
    asm("{ .reg .u64 t; cvta.to.shared.u64 t, %1; cvt.u32.u64 %0, t; }"
        : "=r"(a) : "l"(p));
    return a;
}
__device__ __forceinline__ float dsmem_ld(const float* p, uint32_t rank) {
    uint32_t a = smem_u32(p), r;
    asm("mapa.shared::cluster.u32 %0, %1, %2;" : "=r"(r) : "r"(a), "r"(rank));
    float v;
    asm volatile("ld.shared::cluster.f32 %0, [%1];" : "=f"(v) : "r"(r));
    return v;
}
#define CLUSTER_ARRIVE() asm volatile("barrier.cluster.arrive.aligned;" ::: "memory")
#define CLUSTER_WAIT()   asm volatile("barrier.cluster.wait.aligned;"   ::: "memory")

extern __shared__ float smem[];

// ---------------- main: 8-CTA cluster per image, 2-deep halo, 1 barrier / 2 iters ----------------
__global__ void __launch_bounds__(NTHR, 2) __cluster_dims__(NCTA, 1, 1)
vin_main(const float* __restrict__ input_view,
         const int*   __restrict__ coords,
         const float* __restrict__ q_w,
         const float* __restrict__ w,
         const float* __restrict__ fc_w,
         float*       __restrict__ out)
{
    unsigned long long* cr = (unsigned long long*)smem;   // [(px*5+cp)*256 + tid]
    float* vA   = smem + CR_F;            // 20 rows, idx = global row + 2
    float* vB   = vA + VA_F;              // 18 rows, idx = global row + 1
    float* rs   = vB + VB_F;              // 6 rows: 0..2 = global -2..0 ; 3..5 = 15..17
    float* exp_ = rs + RS_F;              // [par][slot(4)][S]; slots = rows 0,1,14,15
    float* wq_s = exp_ + EXP_F;
    float* wv_s = wq_s + 90;
    float* qfin = wv_s + 90;

    const int tid  = threadIdx.x;
    const int img  = blockIdx.x >> 3;
    const int rank = blockIdx.x & 7;
    const int r0   = rank * RPC;

    // zero vA, vB, rs, exp (halos included)
    for (int i = tid; i < VA_F + VB_F + RS_F + EXP_F; i += NTHR) vA[i] = 0.f;
    if (tid < 90) {
        int c = tid/9, t9 = tid%9, cp = c>>1, half = c&1;
        wq_s[(cp*9 + t9)*2 + half] = q_w[c*9 + t9];
        wv_s[(cp*9 + t9)*2 + half] = w  [c*9 + t9];
    }
    __syncthreads();

    // ---- stage A: r rows [r0-2, r0+17] into vA (temp), zero outside image ----
    {
        float e[19];
        #pragma unroll
        for (int i = 0; i < 19; ++i) e[i] = g_eff[i];
        const float* inb = input_view + (size_t)img * 2 * HS * HS;
        for (int idx = tid; idx < 20*HS; idx += NTHR) {
            int j = idx >> 7, x = idx & 127;
            int gy = r0 - 2 + j;
            float acc = 0.f;
            if ((unsigned)gy < (unsigned)HS) {
                acc = e[18];
                #pragma unroll
                for (int ch = 0; ch < 2; ++ch) {
                    const float* ip = inb + ch*HS*HS;
                    #pragma unroll
                    for (int ky = 0; ky < 3; ++ky) {
                        int yy = gy + ky - 1;
                        if ((unsigned)yy < (unsigned)HS) {
                            #pragma unroll
                            for (int kx = 0; kx < 3; ++kx) {
                                int xx = x + kx - 1;
                                if ((unsigned)xx < (unsigned)HS)
                                    acc += ip[yy*HS + xx] * e[ch*9 + ky*3 + kx];
                            }
                        }
                    }
                }
            }
            vA[j*S + x + 1] = acc;
        }
    }
    __syncthreads();

    const int y  = tid >> 4;          // owned row 0..15
    const int x0 = (tid & 15) << 3;   // 0..120

    // ---- stage B: cr_main = conv(r, q_w), channel-pair u64, transposed layout ----
    {
        unsigned long long rd[3][10];
        #pragma unroll
        for (int rr = 0; rr < 3; ++rr) {
            const float4* p = (const float4*)(vA + (y+1+rr)*S + x0);   // global rows y-1..y+1
            float4 a = p[0], b4 = p[1], c4 = p[2];
            rd[rr][0]=dup2(a.x);  rd[rr][1]=dup2(a.y);  rd[rr][2]=dup2(a.z);  rd[rr][3]=dup2(a.w);
            rd[rr][4]=dup2(b4.x); rd[rr][5]=dup2(b4.y); rd[rr][6]=dup2(b4.z); rd[rr][7]=dup2(b4.w);
            rd[rr][8]=dup2(c4.x); rd[rr][9]=dup2(c4.y);
        }
        #pragma unroll
        for (int cp = 0; cp < 5; ++cp) {
            unsigned long long W[9];
            #pragma unroll
            for (int t9 = 0; t9 < 9; ++t9)
                W[t9] = *(const unsigned long long*)(wq_s + (cp*9 + t9)*2);
            #pragma unroll
            for (int px = 0; px < 8; ++px) {
                unsigned long long acc = mul2(rd[0][px], W[0]);
                acc = fma2(rd[0][px+1], W[1], acc);
                acc = fma2(rd[0][px+2], W[2], acc);
                acc = fma2(rd[1][px],   W[3], acc);
                acc = fma2(rd[1][px+1], W[4], acc);
                acc = fma2(rd[1][px+2], W[5], acc);
                acc = fma2(rd[2][px],   W[6], acc);
                acc = fma2(rd[2][px+1], W[7], acc);
                acc = fma2(rd[2][px+2], W[8], acc);
                cr[(px*5 + cp)*NTHR + tid] = acc;
            }
        }
    }
    __syncthreads();
    // save r boundary strip, then convert vA into the v buffer (zero it)
    for (int i = tid; i < RS_F; i += NTHR) {
        int j = i / S, col = i % S;
        int src = (j < 3) ? j : j + 14;          // vA idx 0..2 and 17..19
        rs[i] = vA[src*S + col];
    }
    __syncthreads();
    for (int i = tid; i < VA_F; i += NTHR) vA[i] = 0.f;
    __syncthreads();

    // ---- 20 blocks of 2 value-iteration sweeps; 1 cluster barrier per block ----
    #pragma unroll 1
    for (int blk = 0; blk < NBLK; ++blk) {
        const int par = blk & 1;

        // ===== iterA: read vA (idx g+2), write vB (idx g+1); also rows -1 and 16 =====
        {
            unsigned long long vd[3][10];
            #pragma unroll
            for (int rr = 0; rr < 3; ++rr) {
                const float4* p = (const float4*)(vA + (y+1+rr)*S + x0);
                float4 a = p[0], b4 = p[1], c4 = p[2];
                vd[rr][0]=dup2(a.x);  vd[rr][1]=dup2(a.y);  vd[rr][2]=dup2(a.z);  vd[rr][3]=dup2(a.w);
                vd[rr][4]=dup2(b4.x); vd[rr][5]=dup2(b4.y); vd[rr][6]=dup2(b4.z); vd[rr][7]=dup2(b4.w);
                vd[rr][8]=dup2(c4.x); vd[rr][9]=dup2(c4.y);
            }
            float vmx[8], vmy[8];
            #pragma unroll
            for (int cp = 0; cp < 5; ++cp) {
                unsigned long long W[9];
                #pragma unroll
                for (int t9 = 0; t9 < 9; ++t9)
                    W[t9] = *(const unsigned long long*)(wv_s + (cp*9 + t9)*2);
                #pragma unroll
                for (int px = 0; px < 8; ++px) {
                    unsigned long long acc = cr[(px*5 + cp)*NTHR + tid];
                    acc = fma2(vd[0][px],   W[0], acc);
                    acc = fma2(vd[0][px+1], W[1], acc);
                    acc = fma2(vd[0][px+2], W[2], acc);
                    acc = fma2(vd[1][px],   W[3], acc);
                    acc = fma2(vd[1][px+1], W[4], acc);
                    acc = fma2(vd[1][px+2], W[5], acc);
                    acc = fma2(vd[2][px],   W[6], acc);
                    acc = fma2(vd[2][px+1], W[7], acc);
                    acc = fma2(vd[2][px+2], W[8], acc);
                    float2 aa = u2f(acc);
                    if (cp == 0) { vmx[px] = aa.x;                 vmy[px] = aa.y; }
                    else         { vmx[px] = fmaxf(vmx[px], aa.x); vmy[px] = fmaxf(vmy[px], aa.y); }
                }
            }
            float* vo = vB + (y+1)*S + x0 + 1;
            #pragma unroll
            for (int px = 0; px < 8; ++px) vo[px] = fmaxf(vmx[px], vmy[px]);
        }
        // extra halo-adjacent rows -1 (tid<128, needs rank>0) and 16 (tid>=128, rank<7)
        {
            const bool top = (tid < 128);
            if (top ? (rank > 0) : (rank < NCTA-1)) {
                const int px  = tid & 127;
                const int va0 = top ? 0 : 17;   // vA idx of patch top (global -2 / 15)
                const int rs0 = top ? 0 : 3;    // r strip idx of patch top
                const int ob  = top ? 0 : 17;   // vB row idx of output (global -1 / 16)
                unsigned long long rp[9], vp[9];
                #pragma unroll
                for (int rr = 0; rr < 3; ++rr)
                    #pragma unroll
                    for (int cc = 0; cc < 3; ++cc) {
                        rp[rr*3+cc] = dup2(rs[(rs0+rr)*S + px + cc]);
                        vp[rr*3+cc] = dup2(vA[(va0+rr)*S + px + cc]);
                    }
                float mx = 0.f, my = 0.f;
                #pragma unroll
                for (int cp = 0; cp < 5; ++cp) {
                    unsigned long long acc = mul2(rp[0], *(const unsigned long long*)(wq_s + (cp*9+0)*2));
                    #pragma unroll
                    for (int t9 = 1; t9 < 9; ++t9)
                        acc = fma2(rp[t9], *(const unsigned long long*)(wq_s + (cp*9+t9)*2), acc);
                    #pragma unroll
                    for (int t9 = 0; t9 < 9; ++t9)
                        acc = fma2(vp[t9], *(const unsigned long long*)(wv_s + (cp*9+t9)*2), acc);
                    float2 aa = u2f(acc);
                    if (cp == 0) { mx = aa.x; my = aa.y; }
                    else         { mx = fmaxf(mx, aa.x); my = fmaxf(my, aa.y); }
                }
                vB[ob*S + px + 1] = fmaxf(mx, my);
            }
        }
        __syncthreads();

        // ===== iterB: read vB (idx g+1), write vA (idx g+2) + export boundary rows =====
        {
            unsigned long long vd[3][10];
            #pragma unroll
            for (int rr = 0; rr < 3; ++rr) {
                const float4* p = (const float4*)(vB + (y+rr)*S + x0);
                float4 a = p[0], b4 = p[1], c4 = p[2];
                vd[rr][0]=dup2(a.x);  vd[rr][1]=dup2(a.y);  vd[rr][2]=dup2(a.z);  vd[rr][3]=dup2(a.w);
                vd[rr][4]=dup2(b4.x); vd[rr][5]=dup2(b4.y); vd[rr][6]=dup2(b4.z); vd[rr][7]=dup2(b4.w);
                vd[rr][8]=dup2(c4.x); vd[rr][9]=dup2(c4.y);
            }
            float vmx[8], vmy[8];
            #pragma unroll
            for (int cp = 0; cp < 5; ++cp) {
                unsigned long long W[9];
                #pragma unroll
                for (int t9 = 0; t9 < 9; ++t9)
                    W[t9] = *(const unsigned long long*)(wv_s + (cp*9 + t9)*2);
                #pragma unroll
                for (int px = 0; px < 8; ++px) {
                    unsigned long long acc = cr[(px*5 + cp)*NTHR + tid];
                    acc = fma2(vd[0][px],   W[0], acc);
                    acc = fma2(vd[0][px+1], W[1], acc);
                    acc = fma2(vd[0][px+2], W[2], acc);
                    acc = fma2(vd[1][px],   W[3], acc);
                    acc = fma2(vd[1][px+1], W[4], acc);
                    acc = fma2(vd[1][px+2], W[5], acc);
                    acc = fma2(vd[2][px],   W[6], acc);
                    acc = fma2(vd[2][px+1], W[7], acc);
                    acc = fma2(vd[2][px+2], W[8], acc);
                    float2 aa = u2f(acc);
                    if (cp == 0) { vmx[px] = aa.x;                 vmy[px] = aa.y; }
                    else         { vmx[px] = fmaxf(vmx[px], aa.x); vmy[px] = fmaxf(vmy[px], aa.y); }
                }
            }
            float* vo = vA + (y+2)*S + x0 + 1;
            float res[8];
            #pragma unroll
            for (int px = 0; px < 8; ++px) { res[px] = fmaxf(vmx[px], vmy[px]); vo[px] = res[px]; }
            // export boundary rows 0,1,14,15 (parity-buffered, race-free)
            if (y == 0 || y == 1 || y == 14 || y == 15) {
                int slot = (y < 2) ? y : y - 12;
                float* e = exp_ + par*(4*S) + slot*S + x0 + 1;
                #pragma unroll
                for (int px = 0; px < 8; ++px) e[px] = res[px];
            }
        }

        // one cluster barrier per 2 iterations, then pull 4 halo rows from exports
        CLUSTER_ARRIVE();
        CLUSTER_WAIT();
        #pragma unroll
        for (int k = 0; k < 2; ++k) {
            int idx = tid + k*NTHR;          // 0..511
            int j   = idx >> 7;              // 0..3
            int px  = idx & 127;
            if (j < 2) {
                if (rank > 0)          // vA rows -2,-1 <- above's rows 14,15 (slots 2,3)
                    vA[j*S + 1 + px] = dsmem_ld(exp_ + par*(4*S) + (2+j)*S + 1 + px, rank - 1);
            } else {
                if (rank < NCTA-1)     // vA rows 16,17 <- below's rows 0,1 (slots 0,1)
                    vA[(16+j)*S + 1 + px] = dsmem_ld(exp_ + par*(4*S) + (j-2)*S + 1 + px, rank + 1);
            }
        }
        __syncthreads();
    }

    // ---- readout: final v in vA (owned rows + freshly pulled halos) ----
    const int sx = coords[img*4 + 0];
    const int sy = coords[img*4 + 1];
    if ((sx >> 4) == rank) {
        const int yl = sx & 15;
        if (tid < 10) {
            int tt = yl*16 + (sy >> 3), slot = sy & 7;
            int cp = tid >> 1, half = tid & 1;
            float2 crv = u2f(cr[(slot*5 + cp)*NTHR + tt]);
            float acc = half ? crv.y : crv.x;
            #pragma unroll
            for (int rr = 0; rr < 3; ++rr)
                #pragma unroll
                for (int cc = 0; cc < 3; ++cc)
                    acc += w[tid*9 + rr*3 + cc] * vA[(yl+1+rr)*S + sy + cc];
            qfin[tid] = acc;
        }
        __syncthreads();
        if (tid < 5) {
            float s = 0.f;
            #pragma unroll
            for (int c = 0; c < 10; ++c) s += qfin[c] * fc_w[tid*10 + c];
            out[img*5 + tid] = s;
        }
    }

    // no CTA may exit while a neighbor's remote read of our export can be in flight
    CLUSTER_ARRIVE();
    CLUSTER_WAIT();
}

extern "C" void kernel_launch(void* const* d_in, const int* in_sizes, int n_in,
                              void* d_out, int out_size) {
    const float* input_view = (const float*)d_in[0];
    const int*   coords     = (const int*)  d_in[1];
    const float* h_w        = (const float*)d_in[2];
    const float* h_b        = (const float*)d_in[3];
    const float* r_w        = (const float*)d_in[4];
    const float* q_w        = (const float*)d_in[5];
    const float* w          = (const float*)d_in[6];
    const float* fc_w       = (const float*)d_in[7];
    float* out = (float*)d_out;

    (void)in_sizes; (void)n_in; (void)out_size;

    vin_prep<<<1, 32>>>(h_w, h_b, r_w);

    cudaFuncSetAttribute(vin_main, cudaFuncAttributeMaxDynamicSharedMemorySize, SMEM_BYTES);
    vin_main<<<NIMG*NCTA, NTHR, SMEM_BYTES>>>(input_view, coords, q_w, w, fc_w, out);
}

// round 8
// speedup vs baseline: 1.0957x; 1.0957x over previous
#include <cuda_runtime.h>
#include <cstdint>

#define HS    128
#define KITER 40
#define NIMG  256
#define RPC   16            // rows per CTA
#define NCTA  8             // cluster size (8 * 16 = 128 rows)
#define S     132           // padded row stride (floats)
#define VROWS 18            // RPC + 2 halo rows
#define NTHR  256

#define CR_F       (5*8*NTHR*2)        // cr: 5cp * 4 pairs * 256 thr * ull2 = 20480 floats
#define VBUF_F     (VROWS*S)           // 2376 floats
#define W_F        100                 // 5 cp * 10 u64-slots * 2 floats
#define SM_FLOATS  (CR_F + 2*VBUF_F + W_F + W_F + 16)
#define SMEM_BYTES (SM_FLOATS*4)

__device__ float g_eff[19];   // collapsed h->r conv weights (18) + bias

// ---------------- prep: collapse h_w/h_b/r_w into 2x3x3 eff conv ----------------
__global__ void vin_prep(const float* __restrict__ h_w,
                         const float* __restrict__ h_b,
                         const float* __restrict__ r_w) {
    int t = threadIdx.x;
    if (t < 18) {
        float s = 0.f;
        for (int c = 0; c < 150; ++c) s += r_w[c] * h_w[c*18 + t];
        g_eff[t] = s;
    } else if (t == 18) {
        float s = 0.f;
        for (int c = 0; c < 150; ++c) s += r_w[c] * h_b[c];
        g_eff[18] = s;
    }
}

// ---------------- f32x2 / PTX helpers ----------------
__device__ __forceinline__ unsigned long long dup2(float x) {
    unsigned long long d;
    asm("mov.b64 %0, {%1, %1};" : "=l"(d) : "f"(x));
    return d;
}
__device__ __forceinline__ unsigned long long fma2(unsigned long long a,
                                                   unsigned long long b,
                                                   unsigned long long c) {
    unsigned long long d;
    asm("fma.rn.f32x2 %0, %1, %2, %3;" : "=l"(d) : "l"(a), "l"(b), "l"(c));
    return d;
}
__device__ __forceinline__ unsigned long long mul2(unsigned long long a,
                                                   unsigned long long b) {
    unsigned long long d;
    asm("mul.rn.f32x2 %0, %1, %2;" : "=l"(d) : "l"(a), "l"(b));
    return d;
}
__device__ __forceinline__ float2 u2f(unsigned long long u) {
    float2 f;
    asm("mov.b64 {%0, %1}, %2;" : "=f"(f.x), "=f"(f.y) : "l"(u));
    return f;
}
__device__ __forceinline__ uint32_t smem_u32(const void* p) {
    uint32_t a;
    asm("{ .reg .u64 t; cvta.to.shared.u64 t, %1; cvt.u32.u64 %0, t; }"
        : "=r"(a) : "l"(p));
    return a;
}
__device__ __forceinline__ float dsmem_ld(const float* p, uint32_t rank) {
    uint32_t a = smem_u32(p), r;
    asm("mapa.shared::cluster.u32 %0, %1, %2;" : "=r"(r) : "r"(a), "r"(rank));
    float v;
    asm volatile("ld.shared::cluster.f32 %0, [%1];" : "=f"(v) : "r"(r));
    return v;
}
#define CLUSTER_ARRIVE() asm volatile("barrier.cluster.arrive.aligned;" ::: "memory")
#define CLUSTER_WAIT()   asm volatile("barrier.cluster.wait.aligned;"   ::: "memory")

extern __shared__ float smem[];

// ---------------- main: 8-CTA cluster per image, 16 rows per CTA ----------------
__global__ void __launch_bounds__(NTHR, 2) __cluster_dims__(NCTA, 1, 1)
vin_main(const float* __restrict__ input_view,
         const int*   __restrict__ coords,
         const float* __restrict__ q_w,
         const float* __restrict__ w,
         const float* __restrict__ fc_w,
         float*       __restrict__ out)
{
    // cr: ulonglong2 per (pair pp, cp, tid): crp[(pp*5+cp)*256 + tid] = {acc_px2pp, acc_px2pp+1}
    ulonglong2* crp = (ulonglong2*)smem;
    float* buf0 = smem + CR_F;
    float* buf1 = buf0 + VBUF_F;
    float* wq_s = buf1 + VBUF_F;   // 5cp * 10 u64-slots (t=0..8 used), 16B-aligned pairs
    float* wv_s = wq_s + W_F;
    float* qfin = wv_s + W_F;

    const int tid  = threadIdx.x;
    const int img  = blockIdx.x >> 3;
    const int rank = blockIdx.x & 7;
    const int r0   = rank * RPC;

    // zero v buffers + weight arrays (unused slots must be 0-initialized deterministically)
    for (int i = tid; i < 2*VBUF_F + 2*W_F; i += NTHR) buf0[i] = 0.f;
    __syncthreads();
    if (tid < 90) {
        int c = tid/9, t9 = tid%9, cp = c>>1, half = c&1;
        wq_s[(cp*10 + t9)*2 + half] = q_w[c*9 + t9];
        wv_s[(cp*10 + t9)*2 + half] = w  [c*9 + t9];
    }
    __syncthreads();

    // ---- stage A: r rows [r0-1, r0+16] into buf1 (temp), zero outside image ----
    {
        float e[19];
        #pragma unroll
        for (int i = 0; i < 19; ++i) e[i] = g_eff[i];
        const float* inb = input_view + (size_t)img * 2 * HS * HS;
        for (int idx = tid; idx < VROWS*HS; idx += NTHR) {
            int j = idx >> 7, x = idx & 127;
            int gy = r0 - 1 + j;
            float acc = 0.f;
            if ((unsigned)gy < (unsigned)HS) {
                acc = e[18];
                #pragma unroll
                for (int ch = 0; ch < 2; ++ch) {
                    const float* ip = inb + ch*HS*HS;
                    #pragma unroll
                    for (int ky = 0; ky < 3; ++ky) {
                        int yy = gy + ky - 1;
                        if ((unsigned)yy < (unsigned)HS) {
                            #pragma unroll
                            for (int kx = 0; kx < 3; ++kx) {
                                int xx = x + kx - 1;
                                if ((unsigned)xx < (unsigned)HS)
                                    acc += ip[yy*HS + xx] * e[ch*9 + ky*3 + kx];
                            }
                        }
                    }
                }
            }
            buf1[j*S + x + 1] = acc;
        }
    }
    __syncthreads();

    const int y  = tid >> 4;          // owned row 0..15
    const int x0 = (tid & 15) << 3;   // 0..120

    // ---- stage B: cr = conv(r, q_w), paired ulonglong2 layout ----
    {
        unsigned long long rd[3][10];
        #pragma unroll
        for (int rr = 0; rr < 3; ++rr) {
            const float4* p = (const float4*)(buf1 + (y+rr)*S + x0);
            float4 a = p[0], b4 = p[1], c4 = p[2];
            rd[rr][0]=dup2(a.x);  rd[rr][1]=dup2(a.y);  rd[rr][2]=dup2(a.z);  rd[rr][3]=dup2(a.w);
            rd[rr][4]=dup2(b4.x); rd[rr][5]=dup2(b4.y); rd[rr][6]=dup2(b4.z); rd[rr][7]=dup2(b4.w);
            rd[rr][8]=dup2(c4.x); rd[rr][9]=dup2(c4.y);
        }
        #pragma unroll
        for (int cp = 0; cp < 5; ++cp) {
            unsigned long long W[9];
            #pragma unroll
            for (int t9 = 0; t9 < 9; ++t9)
                W[t9] = *(const unsigned long long*)(wq_s + (cp*10 + t9)*2);
            unsigned long long acc[8];
            #pragma unroll
            for (int px = 0; px < 8; ++px) {
                unsigned long long a = mul2(rd[0][px], W[0]);
                a = fma2(rd[0][px+1], W[1], a);
                a = fma2(rd[0][px+2], W[2], a);
                a = fma2(rd[1][px],   W[3], a);
                a = fma2(rd[1][px+1], W[4], a);
                a = fma2(rd[1][px+2], W[5], a);
                a = fma2(rd[2][px],   W[6], a);
                a = fma2(rd[2][px+1], W[7], a);
                a = fma2(rd[2][px+2], W[8], a);
                acc[px] = a;
            }
            #pragma unroll
            for (int pp = 0; pp < 4; ++pp)
                crp[(pp*5 + cp)*NTHR + tid] = make_ulonglong2(acc[2*pp], acc[2*pp+1]);
        }
    }
    __syncthreads();
    // buf1 becomes a v buffer: re-zero it
    for (int i = tid; i < VBUF_F; i += NTHR) buf1[i] = 0.f;
    __syncthreads();

    // ---- 40 value-iteration sweeps ----
    #pragma unroll 1
    for (int it = 0; it < KITER; ++it) {
        const float* vc = (it & 1) ? buf1 : buf0;
        float*       vn = (it & 1) ? buf0 : buf1;

        unsigned long long vd[3][10];
        #pragma unroll
        for (int rr = 0; rr < 3; ++rr) {
            const float4* p = (const float4*)(vc + (y+rr)*S + x0);
            float4 a = p[0], b4 = p[1], c4 = p[2];
            vd[rr][0]=dup2(a.x);  vd[rr][1]=dup2(a.y);  vd[rr][2]=dup2(a.z);  vd[rr][3]=dup2(a.w);
            vd[rr][4]=dup2(b4.x); vd[rr][5]=dup2(b4.y); vd[rr][6]=dup2(b4.z); vd[rr][7]=dup2(b4.w);
            vd[rr][8]=dup2(c4.x); vd[rr][9]=dup2(c4.y);
        }

        float vmx[8], vmy[8];
        #pragma unroll
        for (int cp = 0; cp < 5; ++cp) {
            // weights: 4 LDS.128 + 1 LDS.64 (broadcast)
            const ulonglong2* wp = (const ulonglong2*)(wv_s + cp*20);
            ulonglong2 w01 = wp[0], w23 = wp[1], w45 = wp[2], w67 = wp[3];
            unsigned long long W8 = *(const unsigned long long*)(wv_s + cp*20 + 16);
            // cr accumulators: 4 LDS.128
            ulonglong2 c01 = crp[(0*5 + cp)*NTHR + tid];
            ulonglong2 c23 = crp[(1*5 + cp)*NTHR + tid];
            ulonglong2 c45 = crp[(2*5 + cp)*NTHR + tid];
            ulonglong2 c67 = crp[(3*5 + cp)*NTHR + tid];
            unsigned long long acc[8] = {c01.x, c01.y, c23.x, c23.y,
                                         c45.x, c45.y, c67.x, c67.y};
            #pragma unroll
            for (int px = 0; px < 8; ++px) {
                unsigned long long a = acc[px];
                a = fma2(vd[0][px],   w01.x, a);
                a = fma2(vd[0][px+1], w01.y, a);
                a = fma2(vd[0][px+2], w23.x, a);
                a = fma2(vd[1][px],   w23.y, a);
                a = fma2(vd[1][px+1], w45.x, a);
                a = fma2(vd[1][px+2], w45.y, a);
                a = fma2(vd[2][px],   w67.x, a);
                a = fma2(vd[2][px+1], w67.y, a);
                a = fma2(vd[2][px+2], W8,    a);
                float2 aa = u2f(a);
                if (cp == 0) { vmx[px] = aa.x;                 vmy[px] = aa.y; }
                else         { vmx[px] = fmaxf(vmx[px], aa.x); vmy[px] = fmaxf(vmy[px], aa.y); }
            }
        }
        float* vo = vn + (y+1)*S + x0 + 1;
        #pragma unroll
        for (int px = 0; px < 8; ++px) vo[px] = fmaxf(vmx[px], vmy[px]);

        // cluster-wide: everyone finished writing vn; then pull halo rows via DSMEM
        CLUSTER_ARRIVE();
        CLUSTER_WAIT();
        if (tid < 128) {
            if (rank > 0)
                vn[0*S + 1 + tid]       = dsmem_ld(vn + RPC*S + 1 + tid, rank - 1);
        } else {
            int t2 = tid - 128;
            if (rank < NCTA-1)
                vn[(RPC+1)*S + 1 + t2]  = dsmem_ld(vn + 1*S + 1 + t2, rank + 1);
        }
        __syncthreads();
    }

    // ---- readout: final v is buf0 (it=39 wrote buf0) ----
    const int sx = coords[img*4 + 0];
    const int sy = coords[img*4 + 1];
    if ((sx >> 4) == rank) {
        const float* vf = buf0;
        const int yl = sx & 15;
        if (tid < 10) {
            int tt = yl*16 + (sy >> 3), slot = sy & 7;
            int cp = tid >> 1, half = tid & 1;
            ulonglong2 ce = crp[((slot >> 1)*5 + cp)*NTHR + tt];
            float2 crv = u2f((slot & 1) ? ce.y : ce.x);
            float acc = half ? crv.y : crv.x;
            #pragma unroll
            for (int rr = 0; rr < 3; ++rr)
                #pragma unroll
                for (int cc = 0; cc < 3; ++cc)
                    acc += w[tid*9 + rr*3 + cc] * vf[(yl + rr)*S + sy + cc];
            qfin[tid] = acc;
        }
        __syncthreads();
        if (tid < 5) {
            float s = 0.f;
            #pragma unroll
            for (int c = 0; c < 10; ++c) s += qfin[c] * fc_w[tid*10 + c];
            out[img*5 + tid] = s;
        }
    }

    // final cluster barrier: no CTA may exit while a neighbor's remote
    // ld.shared::cluster into this CTA's SMEM could still be in flight
    CLUSTER_ARRIVE();
    CLUSTER_WAIT();
}

extern "C" void kernel_launch(void* const* d_in, const int* in_sizes, int n_in,
                              void* d_out, int out_size) {
    const float* input_view = (const float*)d_in[0];
    const int*   coords     = (const int*)  d_in[1];
    const float* h_w        = (const float*)d_in[2];
    const float* h_b        = (const float*)d_in[3];
    const float* r_w        = (const float*)d_in[4];
    const float* q_w        = (const float*)d_in[5];
    const float* w          = (const float*)d_in[6];
    const float* fc_w       = (const float*)d_in[7];
    float* out = (float*)d_out;

    (void)in_sizes; (void)n_in; (void)out_size;

    vin_prep<<<1, 32>>>(h_w, h_b, r_w);

    cudaFuncSetAttribute(vin_main, cudaFuncAttributeMaxDynamicSharedMemorySize, SMEM_BYTES);
    vin_main<<<NIMG*NCTA, NTHR, SMEM_BYTES>>>(input_view, coords, q_w, w, fc_w, out);
}

// round 9
// speedup vs baseline: 1.1602x; 1.0589x over previous
#include <cuda_runtime.h>
#include <cstdint>

#define HS    128
#define KITER 40
#define NIMG  256
#define RPC   16            // rows per CTA
#define NCTA  8             // cluster size (8 * 16 = 128 rows)
#define S     132           // padded row stride (floats)
#define VROWS 18            // RPC + 2 halo rows
#define NTHR  256

#define MB_F       8                   // 4 mbarriers (u64) = 32 B
#define CR_F       (5*8*NTHR*2)        // cr: 20480 floats (80 KB)
#define VBUF_F     (VROWS*S)           // 2376 floats
#define EXP_F      (4*S)               // exp_top[2 par] + exp_bot[2 par], 1 row each
#define W_F        100                 // 5 cp * 10 u64-slots * 2 floats
#define SM_FLOATS  (MB_F + CR_F + 2*VBUF_F + EXP_F + 2*W_F + 16)
#define SMEM_BYTES (SM_FLOATS*4)

__device__ float g_eff[19];   // collapsed h->r conv weights (18) + bias

// ---------------- prep: collapse h_w/h_b/r_w into 2x3x3 eff conv ----------------
__global__ void vin_prep(const float* __restrict__ h_w,
                         const float* __restrict__ h_b,
                         const float* __restrict__ r_w) {
    int t = threadIdx.x;
    if (t < 18) {
        float s = 0.f;
        for (int c = 0; c < 150; ++c) s += r_w[c] * h_w[c*18 + t];
        g_eff[t] = s;
    } else if (t == 18) {
        float s = 0.f;
        for (int c = 0; c < 150; ++c) s += r_w[c] * h_b[c];
        g_eff[18] = s;
    }
}

// ---------------- f32x2 / PTX helpers ----------------
__device__ __forceinline__ unsigned long long dup2(float x) {
    unsigned long long d;
    asm("mov.b64 %0, {%1, %1};" : "=l"(d) : "f"(x));
    return d;
}
__device__ __forceinline__ unsigned long long fma2(unsigned long long a,
                                                   unsigned long long b,
                                                   unsigned long long c) {
    unsigned long long d;
    asm("fma.rn.f32x2 %0, %1, %2, %3;" : "=l"(d) : "l"(a), "l"(b), "l"(c));
    return d;
}
__device__ __forceinline__ unsigned long long mul2(unsigned long long a,
                                                   unsigned long long b) {
    unsigned long long d;
    asm("mul.rn.f32x2 %0, %1, %2;" : "=l"(d) : "l"(a), "l"(b));
    return d;
}
__device__ __forceinline__ float2 u2f(unsigned long long u) {
    float2 f;
    asm("mov.b64 {%0, %1}, %2;" : "=f"(f.x), "=f"(f.y) : "l"(u));
    return f;
}
__device__ __forceinline__ uint32_t smem_u32(const void* p) {
    uint32_t a;
    asm("{ .reg .u64 t; cvta.to.shared.u64 t, %1; cvt.u32.u64 %0, t; }"
        : "=r"(a) : "l"(p));
    return a;
}
__device__ __forceinline__ uint32_t mapa_rank(uint32_t addr, uint32_t rank) {
    uint32_t r;
    asm("mapa.shared::cluster.u32 %0, %1, %2;" : "=r"(r) : "r"(addr), "r"(rank));
    return r;
}
__device__ __forceinline__ float dsmem_ld(const float* p, uint32_t rank) {
    uint32_t a = smem_u32(p), r;
    asm("mapa.shared::cluster.u32 %0, %1, %2;" : "=r"(r) : "r"(a), "r"(rank));
    float v;
    asm volatile("ld.shared::cluster.f32 %0, [%1];" : "=f"(v) : "r"(r));
    return v;
}
__device__ __forceinline__ void mbar_init(uint32_t addr, uint32_t cnt) {
    asm volatile("mbarrier.init.shared.b64 [%0], %1;" :: "r"(addr), "r"(cnt) : "memory");
}
__device__ __forceinline__ void mbar_arrive_remote(uint32_t local_addr, uint32_t rank) {
    uint32_t raddr = mapa_rank(local_addr, rank);
    asm volatile("mbarrier.arrive.release.cluster.shared::cluster.b64 _, [%0];"
                 :: "r"(raddr) : "memory");
}
__device__ __forceinline__ void mbar_wait(uint32_t addr, uint32_t parity) {
    uint32_t done;
    do {
        asm volatile(
            "{ .reg .pred p;\n"
            "  mbarrier.try_wait.parity.acquire.cluster.shared::cta.b64 p, [%1], %2;\n"
            "  selp.b32 %0, 1, 0, p; }\n"
            : "=r"(done) : "r"(addr), "r"(parity) : "memory");
    } while (!done);
}
#define CLUSTER_SYNC() do { \
    asm volatile("barrier.cluster.arrive.aligned;" ::: "memory"); \
    asm volatile("barrier.cluster.wait.aligned;"   ::: "memory"); \
} while (0)

extern __shared__ float smem[];

// ---------------- main: 8-CTA cluster per image, p2p mbarrier halo handshake ----------------
__global__ void __launch_bounds__(NTHR, 2) __cluster_dims__(NCTA, 1, 1)
vin_main(const float* __restrict__ input_view,
         const int*   __restrict__ coords,
         const float* __restrict__ q_w,
         const float* __restrict__ w,
         const float* __restrict__ fc_w,
         float*       __restrict__ out)
{
    // layout: [4 mbars][cr][buf0][buf1][exp][wq][wv][qfin]
    // mbars: mb_top[b] at +b*8 bytes, mb_bot[b] at +16+b*8 bytes
    ulonglong2* crp = (ulonglong2*)(smem + MB_F);
    float* buf0 = smem + MB_F + CR_F;
    float* buf1 = buf0 + VBUF_F;
    float* exp_ = buf1 + VBUF_F;   // exp_top[par] = exp_+par*S ; exp_bot[par] = exp_+(2+par)*S
    float* wq_s = exp_ + EXP_F;
    float* wv_s = wq_s + W_F;
    float* qfin = wv_s + W_F;

    const int tid  = threadIdx.x;
    const int wid  = tid >> 5;
    const int lid  = tid & 31;
    const int img  = blockIdx.x >> 3;
    const int rank = blockIdx.x & 7;
    const int r0   = rank * RPC;

    const uint32_t mb_base = smem_u32(smem);

    // zero v buffers + exports + weight arrays
    for (int i = tid; i < 2*VBUF_F + EXP_F + 2*W_F; i += NTHR) buf0[i] = 0.f;
    if (tid == 0) {
        mbar_init(mb_base + 0,  1);   // top, slot 0
        mbar_init(mb_base + 8,  1);   // top, slot 1
        mbar_init(mb_base + 16, 1);   // bot, slot 0
        mbar_init(mb_base + 24, 1);   // bot, slot 1
    }
    __syncthreads();
    if (tid < 90) {
        int c = tid/9, t9 = tid%9, cp = c>>1, half = c&1;
        wq_s[(cp*10 + t9)*2 + half] = q_w[c*9 + t9];
        wv_s[(cp*10 + t9)*2 + half] = w  [c*9 + t9];
    }
    __syncthreads();
    CLUSTER_SYNC();   // mbar init visible cluster-wide before any remote arrive

    // ---- stage A: r rows [r0-1, r0+16] into buf1 (temp), zero outside image ----
    {
        float e[19];
        #pragma unroll
        for (int i = 0; i < 19; ++i) e[i] = g_eff[i];
        const float* inb = input_view + (size_t)img * 2 * HS * HS;
        for (int idx = tid; idx < VROWS*HS; idx += NTHR) {
            int j = idx >> 7, x = idx & 127;
            int gy = r0 - 1 + j;
            float acc = 0.f;
            if ((unsigned)gy < (unsigned)HS) {
                acc = e[18];
                #pragma unroll
                for (int ch = 0; ch < 2; ++ch) {
                    const float* ip = inb + ch*HS*HS;
                    #pragma unroll
                    for (int ky = 0; ky < 3; ++ky) {
                        int yy = gy + ky - 1;
                        if ((unsigned)yy < (unsigned)HS) {
                            #pragma unroll
                            for (int kx = 0; kx < 3; ++kx) {
                                int xx = x + kx - 1;
                                if ((unsigned)xx < (unsigned)HS)
                                    acc += ip[yy*HS + xx] * e[ch*9 + ky*3 + kx];
                            }
                        }
                    }
                }
            }
            buf1[j*S + x + 1] = acc;
        }
    }
    __syncthreads();

    const int y  = tid >> 4;          // owned row 0..15
    const int x0 = (tid & 15) << 3;   // 0..120

    // ---- stage B: cr = conv(r, q_w), paired ulonglong2 layout ----
    {
        unsigned long long rd[3][10];
        #pragma unroll
        for (int rr = 0; rr < 3; ++rr) {
            const float4* p = (const float4*)(buf1 + (y+rr)*S + x0);
            float4 a = p[0], b4 = p[1], c4 = p[2];
            rd[rr][0]=dup2(a.x);  rd[rr][1]=dup2(a.y);  rd[rr][2]=dup2(a.z);  rd[rr][3]=dup2(a.w);
            rd[rr][4]=dup2(b4.x); rd[rr][5]=dup2(b4.y); rd[rr][6]=dup2(b4.z); rd[rr][7]=dup2(b4.w);
            rd[rr][8]=dup2(c4.x); rd[rr][9]=dup2(c4.y);
        }
        #pragma unroll
        for (int cp = 0; cp < 5; ++cp) {
            unsigned long long W[9];
            #pragma unroll
            for (int t9 = 0; t9 < 9; ++t9)
                W[t9] = *(const unsigned long long*)(wq_s + (cp*10 + t9)*2);
            unsigned long long acc[8];
            #pragma unroll
            for (int px = 0; px < 8; ++px) {
                unsigned long long a = mul2(rd[0][px], W[0]);
                a = fma2(rd[0][px+1], W[1], a);
                a = fma2(rd[0][px+2], W[2], a);
                a = fma2(rd[1][px],   W[3], a);
                a = fma2(rd[1][px+1], W[4], a);
                a = fma2(rd[1][px+2], W[5], a);
                a = fma2(rd[2][px],   W[6], a);
                a = fma2(rd[2][px+1], W[7], a);
                a = fma2(rd[2][px+2], W[8], a);
                acc[px] = a;
            }
            #pragma unroll
            for (int pp = 0; pp < 4; ++pp)
                crp[(pp*5 + cp)*NTHR + tid] = make_ulonglong2(acc[2*pp], acc[2*pp+1]);
        }
    }
    __syncthreads();
    // buf1 becomes a v buffer: re-zero it
    for (int i = tid; i < VBUF_F; i += NTHR) buf1[i] = 0.f;
    __syncthreads();

    // ---- 40 value-iteration sweeps; p2p handshake, no cluster barrier in loop ----
    #pragma unroll 1
    for (int it = 0; it < KITER; ++it) {
        const float* vc = (it & 1) ? buf1 : buf0;
        float*       vn = (it & 1) ? buf0 : buf1;
        const int b_out = it & 1;

        // boundary warps: wait for neighbor's export of iteration it-1, pull into vc halo
        if (it > 0) {
            const int b_in = (it - 1) & 1;
            const uint32_t par = (uint32_t)(((it - 1) >> 1) & 1);
            if (wid == 0) {
                if (rank > 0) {
                    mbar_wait(mb_base + b_in*8, par);
                    #pragma unroll
                    for (int j = 0; j < 4; ++j) {
                        int xx = lid*4 + j;
                        ((float*)vc)[0*S + 1 + xx] =
                            dsmem_ld(exp_ + (2 + b_in)*S + 1 + xx, rank - 1);  // above's exp_bot
                    }
                }
                __syncwarp();
            } else if (wid == 7) {
                if (rank < NCTA-1) {
                    mbar_wait(mb_base + 16 + b_in*8, par);
                    #pragma unroll
                    for (int j = 0; j < 4; ++j) {
                        int xx = lid*4 + j;
                        ((float*)vc)[(RPC+1)*S + 1 + xx] =
                            dsmem_ld(exp_ + b_in*S + 1 + xx, rank + 1);        // below's exp_top
                    }
                }
                __syncwarp();
            }
        }

        unsigned long long vd[3][10];
        #pragma unroll
        for (int rr = 0; rr < 3; ++rr) {
            const float4* p = (const float4*)(vc + (y+rr)*S + x0);
            float4 a = p[0], b4 = p[1], c4 = p[2];
            vd[rr][0]=dup2(a.x);  vd[rr][1]=dup2(a.y);  vd[rr][2]=dup2(a.z);  vd[rr][3]=dup2(a.w);
            vd[rr][4]=dup2(b4.x); vd[rr][5]=dup2(b4.y); vd[rr][6]=dup2(b4.z); vd[rr][7]=dup2(b4.w);
            vd[rr][8]=dup2(c4.x); vd[rr][9]=dup2(c4.y);
        }

        float vmx[8], vmy[8];
        #pragma unroll
        for (int cp = 0; cp < 5; ++cp) {
            const ulonglong2* wp = (const ulonglong2*)(wv_s + cp*20);
            ulonglong2 w01 = wp[0], w23 = wp[1], w45 = wp[2], w67 = wp[3];
            unsigned long long W8 = *(const unsigned long long*)(wv_s + cp*20 + 16);
            ulonglong2 c01 = crp[(0*5 + cp)*NTHR + tid];
            ulonglong2 c23 = crp[(1*5 + cp)*NTHR + tid];
            ulonglong2 c45 = crp[(2*5 + cp)*NTHR + tid];
            ulonglong2 c67 = crp[(3*5 + cp)*NTHR + tid];
            unsigned long long acc[8] = {c01.x, c01.y, c23.x, c23.y,
                                         c45.x, c45.y, c67.x, c67.y};
            #pragma unroll
            for (int px = 0; px < 8; ++px) {
                unsigned long long a = acc[px];
                a = fma2(vd[0][px],   w01.x, a);
                a = fma2(vd[0][px+1], w01.y, a);
                a = fma2(vd[0][px+2], w23.x, a);
                a = fma2(vd[1][px],   w23.y, a);
                a = fma2(vd[1][px+1], w45.x, a);
                a = fma2(vd[1][px+2], w45.y, a);
                a = fma2(vd[2][px],   w67.x, a);
                a = fma2(vd[2][px+1], w67.y, a);
                a = fma2(vd[2][px+2], W8,    a);
                float2 aa = u2f(a);
                if (cp == 0) { vmx[px] = aa.x;                 vmy[px] = aa.y; }
                else         { vmx[px] = fmaxf(vmx[px], aa.x); vmy[px] = fmaxf(vmy[px], aa.y); }
            }
        }
        float* vo = vn + (y+1)*S + x0 + 1;
        float res[8];
        #pragma unroll
        for (int px = 0; px < 8; ++px) { res[px] = fmaxf(vmx[px], vmy[px]); vo[px] = res[px]; }

        // boundary rows also exported into parity slot (rows 1 and 16 of vn)
        if (y == 0) {
            float* e = exp_ + b_out*S + x0 + 1;            // exp_top[b_out]
            #pragma unroll
            for (int px = 0; px < 8; ++px) e[px] = res[px];
        } else if (y == 15) {
            float* e = exp_ + (2 + b_out)*S + x0 + 1;      // exp_bot[b_out]
            #pragma unroll
            for (int px = 0; px < 8; ++px) e[px] = res[px];
        }

        __syncthreads();   // vn + exports complete CTA-wide

        // signal neighbors: my iteration-it export is ready
        if (tid == 0) {
            if (rank > 0)       mbar_arrive_remote(mb_base + 16 + b_out*8, rank - 1); // their mb_bot
        } else if (tid == NTHR-1) {
            if (rank < NCTA-1)  mbar_arrive_remote(mb_base + b_out*8,      rank + 1); // their mb_top
        }
    }

    // ---- refresh buf0 halo for readout (final v = buf0, written at it=39) ----
    {
        const int b = (KITER - 1) & 1;                       // 1
        const uint32_t par = (uint32_t)(((KITER - 1) >> 1) & 1);  // 1
        if (wid == 0) {
            if (rank > 0) {
                mbar_wait(mb_base + b*8, par);
                #pragma unroll
                for (int j = 0; j < 4; ++j) {
                    int xx = lid*4 + j;
                    buf0[0*S + 1 + xx] = dsmem_ld(exp_ + (2 + b)*S + 1 + xx, rank - 1);
                }
            }
        } else if (wid == 7) {
            if (rank < NCTA-1) {
                mbar_wait(mb_base + 16 + b*8, par);
                #pragma unroll
                for (int j = 0; j < 4; ++j) {
                    int xx = lid*4 + j;
                    buf0[(RPC+1)*S + 1 + xx] = dsmem_ld(exp_ + b*S + 1 + xx, rank + 1);
                }
            }
        }
    }
    __syncthreads();

    // ---- readout ----
    const int sx = coords[img*4 + 0];
    const int sy = coords[img*4 + 1];
    if ((sx >> 4) == rank) {
        const float* vf = buf0;
        const int yl = sx & 15;
        if (tid < 10) {
            int tt = yl*16 + (sy >> 3), slot = sy & 7;
            int cp = tid >> 1, half = tid & 1;
            ulonglong2 ce = crp[((slot >> 1)*5 + cp)*NTHR + tt];
            float2 crv = u2f((slot & 1) ? ce.y : ce.x);
            float acc = half ? crv.y : crv.x;
            #pragma unroll
            for (int rr = 0; rr < 3; ++rr)
                #pragma unroll
                for (int cc = 0; cc < 3; ++cc)
                    acc += w[tid*9 + rr*3 + cc] * vf[(yl + rr)*S + sy + cc];
            qfin[tid] = acc;
        }
        __syncthreads();
        if (tid < 5) {
            float s = 0.f;
            #pragma unroll
            for (int c = 0; c < 10; ++c) s += qfin[c] * fc_w[tid*10 + c];
            out[img*5 + tid] = s;
        }
    }

    // no CTA may exit while a neighbor's remote op targeting it can be in flight
    CLUSTER_SYNC();
}

extern "C" void kernel_launch(void* const* d_in, const int* in_sizes, int n_in,
                              void* d_out, int out_size) {
    const float* input_view = (const float*)d_in[0];
    const int*   coords     = (const int*)  d_in[1];
    const float* h_w        = (const float*)d_in[2];
    const float* h_b        = (const float*)d_in[3];
    const float* r_w        = (const float*)d_in[4];
    const float* q_w        = (const float*)d_in[5];
    const float* w          = (const float*)d_in[6];
    const float* fc_w       = (const float*)d_in[7];
    float* out = (float*)d_out;

    (void)in_sizes; (void)n_in; (void)out_size;

    vin_prep<<<1, 32>>>(h_w, h_b, r_w);

    cudaFuncSetAttribute(vin_main, cudaFuncAttributeMaxDynamicSharedMemorySize, SMEM_BYTES);
    vin_main<<<NIMG*NCTA, NTHR, SMEM_BYTES>>>(input_view, coords, q_w, w, fc_w, out);
}

// round 10
// speedup vs baseline: 1.1825x; 1.0192x over previous
#include <cuda_runtime.h>
#include <cstdint>

#define HS    128
#define KITER 40
#define NIMG  256
#define RPC   16            // rows per CTA
#define NCTA  8             // cluster size (8 * 16 = 128 rows)
#define S     132           // padded row stride (floats)
#define VROWS 18            // RPC + 2 halo rows
#define NTHR  256

#define MB_F       8                   // 4 mbarriers (u64) = 32 B
#define CR_F       (5*8*NTHR*2)        // cr: 20480 floats (80 KB)
#define VBUF_F     (VROWS*S)           // 2376 floats
#define EXP_F      (4*S)               // exp_top[2 par] + exp_bot[2 par]
#define W_F        100                 // 5 cp * 10 u64-slots * 2 floats
#define SM_FLOATS  (MB_F + CR_F + 2*VBUF_F + EXP_F + 2*W_F + 16)
#define SMEM_BYTES (SM_FLOATS*4)

__device__ float g_eff[19];   // collapsed h->r conv weights (18) + bias

// ---------------- prep: collapse h_w/h_b/r_w into 2x3x3 eff conv ----------------
__global__ void vin_prep(const float* __restrict__ h_w,
                         const float* __restrict__ h_b,
                         const float* __restrict__ r_w) {
    int t = threadIdx.x;
    if (t < 18) {
        float s = 0.f;
        for (int c = 0; c < 150; ++c) s += r_w[c] * h_w[c*18 + t];
        g_eff[t] = s;
    } else if (t == 18) {
        float s = 0.f;
        for (int c = 0; c < 150; ++c) s += r_w[c] * h_b[c];
        g_eff[18] = s;
    }
}

// ---------------- f32x2 / PTX helpers ----------------
__device__ __forceinline__ unsigned long long dup2(float x) {
    unsigned long long d;
    asm("mov.b64 %0, {%1, %1};" : "=l"(d) : "f"(x));
    return d;
}
__device__ __forceinline__ unsigned long long fma2(unsigned long long a,
                                                   unsigned long long b,
                                                   unsigned long long c) {
    unsigned long long d;
    asm("fma.rn.f32x2 %0, %1, %2, %3;" : "=l"(d) : "l"(a), "l"(b), "l"(c));
    return d;
}
__device__ __forceinline__ unsigned long long mul2(unsigned long long a,
                                                   unsigned long long b) {
    unsigned long long d;
    asm("mul.rn.f32x2 %0, %1, %2;" : "=l"(d) : "l"(a), "l"(b));
    return d;
}
__device__ __forceinline__ float2 u2f(unsigned long long u) {
    float2 f;
    asm("mov.b64 {%0, %1}, %2;" : "=f"(f.x), "=f"(f.y) : "l"(u));
    return f;
}
__device__ __forceinline__ uint32_t smem_u32(const void* p) {
    uint32_t a;
    asm("{ .reg .u64 t; cvta.to.shared.u64 t, %1; cvt.u32.u64 %0, t; }"
        : "=r"(a) : "l"(p));
    return a;
}
__device__ __forceinline__ uint32_t mapa_rank(uint32_t addr, uint32_t rank) {
    uint32_t r;
    asm("mapa.shared::cluster.u32 %0, %1, %2;" : "=r"(r) : "r"(addr), "r"(rank));
    return r;
}
__device__ __forceinline__ float dsmem_ld(const float* p, uint32_t rank) {
    uint32_t a = smem_u32(p), r;
    asm("mapa.shared::cluster.u32 %0, %1, %2;" : "=r"(r) : "r"(a), "r"(rank));
    float v;
    asm volatile("ld.shared::cluster.f32 %0, [%1];" : "=f"(v) : "r"(r));
    return v;
}
__device__ __forceinline__ void mbar_init(uint32_t addr, uint32_t cnt) {
    asm volatile("mbarrier.init.shared.b64 [%0], %1;" :: "r"(addr), "r"(cnt) : "memory");
}
__device__ __forceinline__ void mbar_arrive_remote(uint32_t local_addr, uint32_t rank) {
    uint32_t raddr = mapa_rank(local_addr, rank);
    asm volatile("mbarrier.arrive.release.cluster.shared::cluster.b64 _, [%0];"
                 :: "r"(raddr) : "memory");
}
__device__ __forceinline__ void mbar_wait(uint32_t addr, uint32_t parity) {
    uint32_t done;
    do {
        asm volatile(
            "{ .reg .pred p;\n"
            "  mbarrier.try_wait.parity.acquire.cluster.shared::cta.b64 p, [%1], %2;\n"
            "  selp.b32 %0, 1, 0, p; }\n"
            : "=r"(done) : "r"(addr), "r"(parity) : "memory");
    } while (!done);
}
__device__ __forceinline__ void named_bar(int id, int nthr) {
    asm volatile("bar.sync %0, %1;" :: "r"(id), "r"(nthr) : "memory");
}
#define CLUSTER_SYNC() do { \
    asm volatile("barrier.cluster.arrive.aligned;" ::: "memory"); \
    asm volatile("barrier.cluster.wait.aligned;"   ::: "memory"); \
} while (0)

extern __shared__ float smem[];

// ---------------- main: 8-CTA cluster, p2p mbarriers + pairwise warp barriers ----------------
__global__ void __launch_bounds__(NTHR, 2) __cluster_dims__(NCTA, 1, 1)
vin_main(const float* __restrict__ input_view,
         const int*   __restrict__ coords,
         const float* __restrict__ q_w,
         const float* __restrict__ w,
         const float* __restrict__ fc_w,
         float*       __restrict__ out)
{
    ulonglong2* crp = (ulonglong2*)(smem + MB_F);
    float* buf0 = smem + MB_F + CR_F;
    float* buf1 = buf0 + VBUF_F;
    float* exp_ = buf1 + VBUF_F;   // exp_top[par]=exp_+par*S ; exp_bot[par]=exp_+(2+par)*S
    float* wq_s = exp_ + EXP_F;
    float* wv_s = wq_s + W_F;
    float* qfin = wv_s + W_F;

    const int tid  = threadIdx.x;
    const int wid  = tid >> 5;
    const int lid  = tid & 31;
    const int img  = blockIdx.x >> 3;
    const int rank = blockIdx.x & 7;
    const int r0   = rank * RPC;

    const uint32_t mb_base = smem_u32(smem);

    for (int i = tid; i < 2*VBUF_F + EXP_F + 2*W_F; i += NTHR) buf0[i] = 0.f;
    if (tid == 0) {
        mbar_init(mb_base + 0,  1);   // top, slot 0
        mbar_init(mb_base + 8,  1);   // top, slot 1
        mbar_init(mb_base + 16, 1);   // bot, slot 0
        mbar_init(mb_base + 24, 1);   // bot, slot 1
    }
    __syncthreads();
    if (tid < 90) {
        int c = tid/9, t9 = tid%9, cp = c>>1, half = c&1;
        wq_s[(cp*10 + t9)*2 + half] = q_w[c*9 + t9];
        wv_s[(cp*10 + t9)*2 + half] = w  [c*9 + t9];
    }
    __syncthreads();
    CLUSTER_SYNC();   // mbar init visible cluster-wide before any remote arrive

    // ---- stage A: r rows [r0-1, r0+16] into buf1 (temp) ----
    {
        float e[19];
        #pragma unroll
        for (int i = 0; i < 19; ++i) e[i] = g_eff[i];
        const float* inb = input_view + (size_t)img * 2 * HS * HS;
        for (int idx = tid; idx < VROWS*HS; idx += NTHR) {
            int j = idx >> 7, x = idx & 127;
            int gy = r0 - 1 + j;
            float acc = 0.f;
            if ((unsigned)gy < (unsigned)HS) {
                acc = e[18];
                #pragma unroll
                for (int ch = 0; ch < 2; ++ch) {
                    const float* ip = inb + ch*HS*HS;
                    #pragma unroll
                    for (int ky = 0; ky < 3; ++ky) {
                        int yy = gy + ky - 1;
                        if ((unsigned)yy < (unsigned)HS) {
                            #pragma unroll
                            for (int kx = 0; kx < 3; ++kx) {
                                int xx = x + kx - 1;
                                if ((unsigned)xx < (unsigned)HS)
                                    acc += ip[yy*HS + xx] * e[ch*9 + ky*3 + kx];
                            }
                        }
                    }
                }
            }
            buf1[j*S + x + 1] = acc;
        }
    }
    __syncthreads();

    const int y  = tid >> 4;          // owned row 0..15
    const int x0 = (tid & 15) << 3;   // 0..120

    // ---- stage B: cr = conv(r, q_w), paired ulonglong2 layout ----
    {
        unsigned long long rd[3][10];
        #pragma unroll
        for (int rr = 0; rr < 3; ++rr) {
            const float4* p = (const float4*)(buf1 + (y+rr)*S + x0);
            float4 a = p[0], b4 = p[1], c4 = p[2];
            rd[rr][0]=dup2(a.x);  rd[rr][1]=dup2(a.y);  rd[rr][2]=dup2(a.z);  rd[rr][3]=dup2(a.w);
            rd[rr][4]=dup2(b4.x); rd[rr][5]=dup2(b4.y); rd[rr][6]=dup2(b4.z); rd[rr][7]=dup2(b4.w);
            rd[rr][8]=dup2(c4.x); rd[rr][9]=dup2(c4.y);
        }
        #pragma unroll
        for (int cp = 0; cp < 5; ++cp) {
            unsigned long long W[9];
            #pragma unroll
            for (int t9 = 0; t9 < 9; ++t9)
                W[t9] = *(const unsigned long long*)(wq_s + (cp*10 + t9)*2);
            unsigned long long acc[8];
            #pragma unroll
            for (int px = 0; px < 8; ++px) {
                unsigned long long a = mul2(rd[0][px], W[0]);
                a = fma2(rd[0][px+1], W[1], a);
                a = fma2(rd[0][px+2], W[2], a);
                a = fma2(rd[1][px],   W[3], a);
                a = fma2(rd[1][px+1], W[4], a);
                a = fma2(rd[1][px+2], W[5], a);
                a = fma2(rd[2][px],   W[6], a);
                a = fma2(rd[2][px+1], W[7], a);
                a = fma2(rd[2][px+2], W[8], a);
                acc[px] = a;
            }
            #pragma unroll
            for (int pp = 0; pp < 4; ++pp)
                crp[(pp*5 + cp)*NTHR + tid] = make_ulonglong2(acc[2*pp], acc[2*pp+1]);
        }
    }
    __syncthreads();
    for (int i = tid; i < VBUF_F; i += NTHR) buf1[i] = 0.f;
    __syncthreads();

    // ---- 40 sweeps; pairwise warp barriers instead of CTA-wide syncthreads ----
    #pragma unroll 1
    for (int it = 0; it < KITER; ++it) {
        const float* vc = (it & 1) ? buf1 : buf0;
        float*       vn = (it & 1) ? buf0 : buf1;
        const int b_out = it & 1;

        // edge warps: wait for neighbor's export of it-1, pull into vc halo row
        if (it > 0) {
            const int b_in = (it - 1) & 1;
            const uint32_t par = (uint32_t)(((it - 1) >> 1) & 1);
            if (wid == 0) {
                if (rank > 0) {
                    mbar_wait(mb_base + b_in*8, par);
                    #pragma unroll
                    for (int j = 0; j < 4; ++j) {
                        int xx = lid*4 + j;
                        ((float*)vc)[0*S + 1 + xx] =
                            dsmem_ld(exp_ + (2 + b_in)*S + 1 + xx, rank - 1);
                    }
                }
                __syncwarp();
            } else if (wid == 7) {
                if (rank < NCTA-1) {
                    mbar_wait(mb_base + 16 + b_in*8, par);
                    #pragma unroll
                    for (int j = 0; j < 4; ++j) {
                        int xx = lid*4 + j;
                        ((float*)vc)[(RPC+1)*S + 1 + xx] =
                            dsmem_ld(exp_ + b_in*S + 1 + xx, rank + 1);
                    }
                }
                __syncwarp();
            }
        }

        unsigned long long vd[3][10];
        #pragma unroll
        for (int rr = 0; rr < 3; ++rr) {
            const float4* p = (const float4*)(vc + (y+rr)*S + x0);
            float4 a = p[0], b4 = p[1], c4 = p[2];
            vd[rr][0]=dup2(a.x);  vd[rr][1]=dup2(a.y);  vd[rr][2]=dup2(a.z);  vd[rr][3]=dup2(a.w);
            vd[rr][4]=dup2(b4.x); vd[rr][5]=dup2(b4.y); vd[rr][6]=dup2(b4.z); vd[rr][7]=dup2(b4.w);
            vd[rr][8]=dup2(c4.x); vd[rr][9]=dup2(c4.y);
        }

        float vmx[8], vmy[8];
        #pragma unroll
        for (int cp = 0; cp < 5; ++cp) {
            const ulonglong2* wp = (const ulonglong2*)(wv_s + cp*20);
            ulonglong2 w01 = wp[0], w23 = wp[1], w45 = wp[2], w67 = wp[3];
            unsigned long long W8 = *(const unsigned long long*)(wv_s + cp*20 + 16);
            ulonglong2 c01 = crp[(0*5 + cp)*NTHR + tid];
            ulonglong2 c23 = crp[(1*5 + cp)*NTHR + tid];
            ulonglong2 c45 = crp[(2*5 + cp)*NTHR + tid];
            ulonglong2 c67 = crp[(3*5 + cp)*NTHR + tid];
            unsigned long long acc[8] = {c01.x, c01.y, c23.x, c23.y,
                                         c45.x, c45.y, c67.x, c67.y};
            #pragma unroll
            for (int px = 0; px < 8; ++px) {
                unsigned long long a = acc[px];
                a = fma2(vd[0][px],   w01.x, a);
                a = fma2(vd[0][px+1], w01.y, a);
                a = fma2(vd[0][px+2], w23.x, a);
                a = fma2(vd[1][px],   w23.y, a);
                a = fma2(vd[1][px+1], w45.x, a);
                a = fma2(vd[1][px+2], w45.y, a);
                a = fma2(vd[2][px],   w67.x, a);
                a = fma2(vd[2][px+1], w67.y, a);
                a = fma2(vd[2][px+2], W8,    a);
                float2 aa = u2f(a);
                if (cp == 0) { vmx[px] = aa.x;                 vmy[px] = aa.y; }
                else         { vmx[px] = fmaxf(vmx[px], aa.x); vmy[px] = fmaxf(vmy[px], aa.y); }
            }
        }
        float* vo = vn + (y+1)*S + x0 + 1;
        float res[8];
        #pragma unroll
        for (int px = 0; px < 8; ++px) { res[px] = fmaxf(vmx[px], vmy[px]); vo[px] = res[px]; }

        // edge-row exports into parity slots
        if (y == 0) {
            if (rank > 0) {
                float* e = exp_ + b_out*S + x0 + 1;
                #pragma unroll
                for (int px = 0; px < 8; ++px) e[px] = res[px];
            }
        } else if (y == 15) {
            if (rank < NCTA-1) {
                float* e = exp_ + (2 + b_out)*S + x0 + 1;
                #pragma unroll
                for (int px = 0; px < 8; ++px) e[px] = res[px];
            }
        }

        // edge warps: signal neighbor (release-arrive after export)
        if (wid == 0) {
            __syncwarp();
            if (lid == 0 && rank > 0)
                mbar_arrive_remote(mb_base + 16 + b_out*8, rank - 1);  // their mb_bot
        } else if (wid == 7) {
            __syncwarp();
            if (lid == 0 && rank < NCTA-1)
                mbar_arrive_remote(mb_base + b_out*8, rank + 1);        // their mb_top
        }

        // pairwise warp barriers: id b joins warps b-1 and b (64 threads).
        // odd ids first, then even ids -> deadlock-free two-phase schedule.
        if (wid & 1) {
            named_bar(wid, 64);
            if (wid < 7) named_bar(wid + 1, 64);
        } else {
            if (wid < 7) named_bar(wid + 1, 64);
            if (wid > 0) named_bar(wid, 64);
        }
    }

    // ---- refresh buf0 halo for readout (final v = buf0, exported at it=39) ----
    {
        const int b = (KITER - 1) & 1;                            // 1
        const uint32_t par = (uint32_t)(((KITER - 1) >> 1) & 1);  // 1
        if (wid == 0) {
            if (rank > 0) {
                mbar_wait(mb_base + b*8, par);
                #pragma unroll
                for (int j = 0; j < 4; ++j) {
                    int xx = lid*4 + j;
                    buf0[0*S + 1 + xx] = dsmem_ld(exp_ + (2 + b)*S + 1 + xx, rank - 1);
                }
            }
        } else if (wid == 7) {
            if (rank < NCTA-1) {
                mbar_wait(mb_base + 16 + b*8, par);
                #pragma unroll
                for (int j = 0; j < 4; ++j) {
                    int xx = lid*4 + j;
                    buf0[(RPC+1)*S + 1 + xx] = dsmem_ld(exp_ + b*S + 1 + xx, rank + 1);
                }
            }
        }
    }
    __syncthreads();

    // ---- readout ----
    const int sx = coords[img*4 + 0];
    const int sy = coords[img*4 + 1];
    if ((sx >> 4) == rank) {
        const float* vf = buf0;
        const int yl = sx & 15;
        if (tid < 10) {
            int tt = yl*16 + (sy >> 3), slot = sy & 7;
            int cp = tid >> 1, half = tid & 1;
            ulonglong2 ce = crp[((slot >> 1)*5 + cp)*NTHR + tt];
            float2 crv = u2f((slot & 1) ? ce.y : ce.x);
            float acc = half ? crv.y : crv.x;
            #pragma unroll
            for (int rr = 0; rr < 3; ++rr)
                #pragma unroll
                for (int cc = 0; cc < 3; ++cc)
                    acc += w[tid*9 + rr*3 + cc] * vf[(yl + rr)*S + sy + cc];
            qfin[tid] = acc;
        }
        __syncthreads();
        if (tid < 5) {
            float s = 0.f;
            #pragma unroll
            for (int c = 0; c < 10; ++c) s += qfin[c] * fc_w[tid*10 + c];
            out[img*5 + tid] = s;
        }
    }

    // no CTA may exit while a neighbor's remote op targeting it can be in flight
    CLUSTER_SYNC();
}

extern "C" void kernel_launch(void* const* d_in, const int* in_sizes, int n_in,
                              void* d_out, int out_size) {
    const float* input_view = (const float*)d_in[0];
    const int*   coords     = (const int*)  d_in[1];
    const float* h_w        = (const float*)d_in[2];
    const float* h_b        = (const float*)d_in[3];
    const float* r_w        = (const float*)d_in[4];
    const float* q_w        = (const float*)d_in[5];
    const float* w          = (const float*)d_in[6];
    const float* fc_w       = (const float*)d_in[7];
    float* out = (float*)d_out;

    (void)in_sizes; (void)n_in; (void)out_size;

    vin_prep<<<1, 32>>>(h_w, h_b, r_w);

    cudaFuncSetAttribute(vin_main, cudaFuncAttributeMaxDynamicSharedMemorySize, SMEM_BYTES);
    vin_main<<<NIMG*NCTA, NTHR, SMEM_BYTES>>>(input_view, coords, q_w, w, fc_w, out);
}